// round 12
// baseline (speedup 1.0000x reference)
#include <cuda_runtime.h>
#include <cstdint>

// YOLO loss "slim2": no smem staging, no barriers; 2 adjacent cells per thread
// with all 10 always-needed scalars front-batched; 6 CTAs/SM for deep MLP.

#define THREADS   256
#define NPART_MAX 2048

__device__ float        g_part[6][NPART_MAX];
__device__ unsigned int g_count = 0;

__device__ __forceinline__ void block_reduce6(float* vals, float* s_red, int tid)
{
    #pragma unroll
    for (int v = 0; v < 6; v++) {
        #pragma unroll
        for (int off = 16; off > 0; off >>= 1)
            vals[v] += __shfl_down_sync(0xffffffffu, vals[v], off);
    }
    const int warp = tid >> 5;
    const int lane = tid & 31;
    if (lane == 0) {
        #pragma unroll
        for (int v = 0; v < 6; v++) s_red[warp * 6 + v] = vals[v];
    }
    __syncthreads();
    if (tid == 0) {
        #pragma unroll
        for (int v = 0; v < 6; v++) {
            float s = 0.f;
            #pragma unroll
            for (int w2 = 0; w2 < THREADS / 32; w2++) s += s_red[w2 * 6 + v];
            vals[v] = s;
        }
    }
}

// obj-cell heavy path (rows mostly L1/L2-resident already)
__device__ __forceinline__ void obj_path(const float* __restrict__ p,
                                         const float* __restrict__ t,
                                         bool c, float p4, float p9,
                                         float t4, float t9, float acc[6])
{
    const int o = c ? 0 : 5;
    acc[4] += 1.f;

    float dx = p[o + 0] - t[o + 0];
    float dy = p[o + 1] - t[o + 1];
    float dw = p[o + 2] - sqrtf(t[o + 2]);
    float dh = p[o + 3] - sqrtf(t[o + 3]);
    acc[0] += 0.5f * (dx * dx + dy * dy) + 0.5f * (dw * dw + dh * dh);

    float d = (c ? p4 : p9) - (c ? t4 : t9);
    acc[2] += d * d;

    // class logits: 10 aligned float2 loads (offset 40B within 120B row)
    float x[20];
    const float2* pc2 = (const float2*)(p + 10);
    #pragma unroll
    for (int k = 0; k < 10; k++) {
        float2 v = pc2[k];
        x[2 * k]     = v.x;
        x[2 * k + 1] = v.y;
    }
    float mx = -1e30f;
    #pragma unroll
    for (int k = 0; k < 20; k++) mx = fmaxf(mx, x[k]);
    float den = 0.f;
    #pragma unroll
    for (int k = 0; k < 20; k++) den += __expf(x[k] - mx);
    float inv = __fdividef(1.f, den);
    float den2 = 0.f;
    #pragma unroll
    for (int k = 0; k < 20; k++) den2 += __expf(__expf(x[k] - mx) * inv);
    float lse2 = __logf(den2);

    const float2* tc2 = (const float2*)(t + 10);
    float bm = -1e30f, xsel = 0.f;
    #pragma unroll
    for (int k = 0; k < 10; k++) {
        float2 v = tc2[k];
        if (v.x > bm) { bm = v.x; xsel = x[2 * k]; }
        if (v.y > bm) { bm = v.y; xsel = x[2 * k + 1]; }
    }
    acc[1] += lse2 - __expf(xsel - mx) * inv;
}

__global__ __launch_bounds__(THREADS, 6)
void yolo_slim2(const float* __restrict__ pred,
                const float* __restrict__ target,
                const int*   __restrict__ choice,
                float*       __restrict__ out,
                int n_cells)
{
    __shared__ float s_red[(THREADS / 32) * 6];
    __shared__ bool  s_last;

    const int tid = threadIdx.x;
    float acc[6] = {0.f, 0.f, 0.f, 0.f, 0.f, 0.f};

    const long long n_pairs = (long long)n_cells >> 1;
    const long long stride  = (long long)gridDim.x * THREADS;

    for (long long pi = (long long)blockIdx.x * THREADS + tid;
         pi < n_pairs; pi += stride)
    {
        const long long c0 = pi * 2;
        const float* p0 = pred   + c0 * 30;
        const float* t0 = target + c0 * 30;
        const float* p1 = p0 + 30;
        const float* t1 = t0 + 30;

        // front-batched always-needed scalars for both cells (10 loads + 1 vec)
        const float a_t4 = t0[4];
        const float b_t4 = t1[4];
        const int2  cv   = *(const int2*)(choice + c0);   // 8B aligned (c0 even)
        const float a_p4 = p0[4];
        const float a_p9 = p0[9];
        const float a_t9 = t0[9];
        const float b_p4 = p1[4];
        const float b_p9 = p1[9];
        const float b_t9 = t1[9];

        if (a_t4 > 0.f) {
            obj_path(p0, t0, cv.x != 0, a_p4, a_p9, a_t4, a_t9, acc);
        } else {
            acc[5] += 1.f;
            float d0 = a_p4 - a_t4;
            float d1 = a_p9 - a_t9;
            acc[3] += d0 * d0 + d1 * d1;
        }
        if (b_t4 > 0.f) {
            obj_path(p1, t1, cv.y != 0, b_p4, b_p9, b_t4, b_t9, acc);
        } else {
            acc[5] += 1.f;
            float d0 = b_p4 - b_t4;
            float d1 = b_p9 - b_t9;
            acc[3] += d0 * d0 + d1 * d1;
        }
    }

    // odd tail cell (none for this shape)
    if ((n_cells & 1) && blockIdx.x == 0 && tid == 0) {
        long long cell = (long long)n_cells - 1;
        const float* p = pred   + cell * 30;
        const float* t = target + cell * 30;
        float t4 = t[4];
        if (t4 > 0.f) {
            obj_path(p, t, choice[cell] != 0, p[4], p[9], t4, t[9], acc);
        } else {
            acc[5] += 1.f;
            float d0 = p[4] - t4;
            float d1 = p[9] - t[9];
            acc[3] += d0 * d0 + d1 * d1;
        }
    }

    __syncthreads();
    block_reduce6(acc, s_red, tid);

    if (tid == 0) {
        #pragma unroll
        for (int v = 0; v < 6; v++) g_part[v][blockIdx.x] = acc[v];
        __threadfence();
        unsigned int ticket = atomicAdd(&g_count, 1u);
        s_last = (ticket == gridDim.x - 1);
    }
    __syncthreads();

    if (s_last) {
        __threadfence();
        const int npart = gridDim.x;
        float a[6] = {0.f, 0.f, 0.f, 0.f, 0.f, 0.f};
        for (int i = tid; i < npart; i += THREADS) {
            #pragma unroll
            for (int v = 0; v < 6; v++) a[v] += g_part[v][i];
        }
        __syncthreads();
        block_reduce6(a, s_red, tid);
        if (tid == 0) {
            float n_obj = fmaxf(a[4], 1.f);
            float n_no  = fmaxf(a[5], 1.f);
            out[0] = 5.0f * a[0];          // loc_loss
            out[1] = a[1] / n_obj;         // cls_loss
            out[2] = a[2];                 // obj_loss
            out[3] = 0.5f * a[3] / n_no;   // noobj_loss
            g_count = 0;                   // reset for next graph replay
        }
    }
}

extern "C" void kernel_launch(void* const* d_in, const int* in_sizes, int n_in,
                              void* d_out, int out_size)
{
    const float* pred   = (const float*)d_in[0];
    const float* target = (const float*)d_in[1];
    const int*   choice = (const int*)d_in[2];
    float* out = (float*)d_out;

    const int n_cells = in_sizes[2];

    int grid = 6 * 148;                      // 6 CTAs/SM x 256 thr = 48 warps/SM
    long long want = (((long long)n_cells >> 1) + THREADS - 1) / THREADS;
    if ((long long)grid > want) grid = (int)want;
    if (grid < 1) grid = 1;
    if (grid > NPART_MAX) grid = NPART_MAX;

    yolo_slim2<<<grid, THREADS>>>(pred, target, choice, out, n_cells);
}

// round 13
// speedup vs baseline: 1.3438x; 1.3438x over previous
#include <cuda_runtime.h>
#include <cstdint>

// YOLO loss "slim3": R10 structure (no smem staging, no barriers, warp-
// contiguous cells) + 2-iteration software pipelining: scalars for cell i and
// cell i+stride are front-batched before either branch, doubling MLP on the
// critical chain. launch_bounds(256,3) keeps regs ~85 (no spills).

#define THREADS   256
#define NPART_MAX 2048

__device__ float        g_part[6][NPART_MAX];
__device__ unsigned int g_count = 0;

__device__ __forceinline__ void block_reduce6(float* vals, float* s_red, int tid)
{
    #pragma unroll
    for (int v = 0; v < 6; v++) {
        #pragma unroll
        for (int off = 16; off > 0; off >>= 1)
            vals[v] += __shfl_down_sync(0xffffffffu, vals[v], off);
    }
    const int warp = tid >> 5;
    const int lane = tid & 31;
    if (lane == 0) {
        #pragma unroll
        for (int v = 0; v < 6; v++) s_red[warp * 6 + v] = vals[v];
    }
    __syncthreads();
    if (tid == 0) {
        #pragma unroll
        for (int v = 0; v < 6; v++) {
            float s = 0.f;
            #pragma unroll
            for (int w2 = 0; w2 < THREADS / 32; w2++) s += s_red[w2 * 6 + v];
            vals[v] = s;
        }
    }
}

// obj-cell heavy path
__device__ __forceinline__ void obj_path(const float* __restrict__ p,
                                         const float* __restrict__ t,
                                         bool c, float p4, float p9,
                                         float t4, float t9, float acc[6])
{
    const int o = c ? 0 : 5;
    acc[4] += 1.f;

    float dx = p[o + 0] - t[o + 0];
    float dy = p[o + 1] - t[o + 1];
    float dw = p[o + 2] - sqrtf(t[o + 2]);
    float dh = p[o + 3] - sqrtf(t[o + 3]);
    acc[0] += 0.5f * (dx * dx + dy * dy) + 0.5f * (dw * dw + dh * dh);

    float d = (c ? p4 : p9) - (c ? t4 : t9);
    acc[2] += d * d;

    // class logits: 10 aligned float2 loads (offset 40B within 120B row)
    float x[20];
    const float2* pc2 = (const float2*)(p + 10);
    #pragma unroll
    for (int k = 0; k < 10; k++) {
        float2 v = pc2[k];
        x[2 * k]     = v.x;
        x[2 * k + 1] = v.y;
    }
    float mx = -1e30f;
    #pragma unroll
    for (int k = 0; k < 20; k++) mx = fmaxf(mx, x[k]);
    float den = 0.f;
    #pragma unroll
    for (int k = 0; k < 20; k++) den += __expf(x[k] - mx);
    float inv = __fdividef(1.f, den);
    // sum exp(sm_k); sm in [0,1] -> shiftless LSE safe (validated)
    float den2 = 0.f;
    #pragma unroll
    for (int k = 0; k < 20; k++) den2 += __expf(__expf(x[k] - mx) * inv);
    float lse2 = __logf(den2);

    const float2* tc2 = (const float2*)(t + 10);
    float bm = -1e30f, xsel = 0.f;
    #pragma unroll
    for (int k = 0; k < 10; k++) {
        float2 v = tc2[k];
        if (v.x > bm) { bm = v.x; xsel = x[2 * k]; }
        if (v.y > bm) { bm = v.y; xsel = x[2 * k + 1]; }
    }
    acc[1] += lse2 - __expf(xsel - mx) * inv;
}

__device__ __forceinline__ void one_cell(const float* __restrict__ p,
                                         const float* __restrict__ t,
                                         int cv, float p4, float p9,
                                         float t4, float t9, float acc[6])
{
    if (t4 > 0.f) {
        obj_path(p, t, cv != 0, p4, p9, t4, t9, acc);
    } else {
        acc[5] += 1.f;
        float d0 = p4 - t4;
        float d1 = p9 - t9;
        acc[3] += d0 * d0 + d1 * d1;
    }
}

__global__ __launch_bounds__(THREADS, 3)
void yolo_slim3(const float* __restrict__ pred,
                const float* __restrict__ target,
                const int*   __restrict__ choice,
                float*       __restrict__ out,
                int n_cells)
{
    __shared__ float s_red[(THREADS / 32) * 6];
    __shared__ bool  s_last;

    const int tid = threadIdx.x;
    float acc[6] = {0.f, 0.f, 0.f, 0.f, 0.f, 0.f};

    const long long stride = (long long)gridDim.x * THREADS;
    long long cell = (long long)blockIdx.x * THREADS + tid;

    // paired iterations: scalars for (cell, cell+stride) front-batched
    for (; cell + stride < n_cells; cell += 2 * stride) {
        const long long cb = cell + stride;
        const float* pA = pred   + cell * 30;
        const float* tA = target + cell * 30;
        const float* pB = pred   + cb * 30;
        const float* tB = target + cb * 30;

        // 10 independent scalar loads + 2 choice loads, all before any branch
        const float a_t4 = tA[4];
        const float b_t4 = tB[4];
        const int   a_cv = choice[cell];
        const int   b_cv = choice[cb];
        const float a_p4 = pA[4];
        const float b_p4 = pB[4];
        const float a_p9 = pA[9];
        const float b_p9 = pB[9];
        const float a_t9 = tA[9];
        const float b_t9 = tB[9];

        one_cell(pA, tA, a_cv, a_p4, a_p9, a_t4, a_t9, acc);
        one_cell(pB, tB, b_cv, b_p4, b_p9, b_t4, b_t9, acc);
    }
    // remainder (0 or 1 iteration)
    for (; cell < n_cells; cell += stride) {
        const float* p = pred   + cell * 30;
        const float* t = target + cell * 30;
        one_cell(p, t, choice[cell], p[4], p[9], t[4], t[9], acc);
    }

    __syncthreads();
    block_reduce6(acc, s_red, tid);

    if (tid == 0) {
        #pragma unroll
        for (int v = 0; v < 6; v++) g_part[v][blockIdx.x] = acc[v];
        __threadfence();
        unsigned int ticket = atomicAdd(&g_count, 1u);
        s_last = (ticket == gridDim.x - 1);
    }
    __syncthreads();

    if (s_last) {
        __threadfence();
        const int npart = gridDim.x;
        float a[6] = {0.f, 0.f, 0.f, 0.f, 0.f, 0.f};
        for (int i = tid; i < npart; i += THREADS) {
            #pragma unroll
            for (int v = 0; v < 6; v++) a[v] += g_part[v][i];
        }
        __syncthreads();
        block_reduce6(a, s_red, tid);
        if (tid == 0) {
            float n_obj = fmaxf(a[4], 1.f);
            float n_no  = fmaxf(a[5], 1.f);
            out[0] = 5.0f * a[0];          // loc_loss
            out[1] = a[1] / n_obj;         // cls_loss
            out[2] = a[2];                 // obj_loss
            out[3] = 0.5f * a[3] / n_no;   // noobj_loss
            g_count = 0;                   // reset for next graph replay
        }
    }
}

extern "C" void kernel_launch(void* const* d_in, const int* in_sizes, int n_in,
                              void* d_out, int out_size)
{
    const float* pred   = (const float*)d_in[0];
    const float* target = (const float*)d_in[1];
    const int*   choice = (const int*)d_in[2];
    float* out = (float*)d_out;

    const int n_cells = in_sizes[2];

    int grid = 3 * 148;                      // 3 CTAs/SM x 256 thr (regs ~85)
    long long want = ((long long)n_cells + THREADS - 1) / THREADS;
    if ((long long)grid > want) grid = (int)want;
    if (grid < 1) grid = 1;
    if (grid > NPART_MAX) grid = NPART_MAX;

    yolo_slim3<<<grid, THREADS>>>(pred, target, choice, out, n_cells);
}